// round 12
// baseline (speedup 1.0000x reference)
#include <cuda_runtime.h>
#include <cuda_fp16.h>
#include <cstdint>

#define NN   4096
#define FIN  256
#define NH   4
#define DHH  64
#define NW   (NN / 32)      // 128 adj-mask words per row
#define NSPLIT 4

// ------------------------- device globals (no alloc allowed) ---------------
__device__ __half g_hTh[NH * DHH * NN];   // hT[head][d][n] fp16
__device__ float  g_ssrc[NH * NN];
__device__ float  g_E[NH * NN];           // exp(s_src)
__device__ float  g_e[NH * NN];           // exp(0.01*s_src)
__device__ __half g_t_h[NH * NN];         // s_dst (half)
__device__ __half g_F_h[NH * NN];         // exp(s_dst)
__device__ __half g_f_h[NH * NN];         // exp(0.01*s_dst)
__device__ unsigned g_adjm[NN * NW];      // adjacency bitmask
__device__ float  g_acc[NSPLIT * NH * NN * DHH];  // unnormalized partials
__device__ float  g_rsp[NSPLIT * NH * NN];        // rowsum partials

// ------------------------- helpers -----------------------------------------
__device__ __forceinline__ uint32_t smem_u32(const void* p) {
    uint32_t a;
    asm("{ .reg .u64 t; cvta.to.shared.u64 t, %1; cvt.u32.u64 %0, t; }"
        : "=r"(a) : "l"(p));
    return a;
}
__device__ __forceinline__ __half2 u2h(uint32_t u) {
    union { uint32_t u; __half2 h; } c; c.u = u; return c.h;
}
__device__ __forceinline__ uint32_t h2u(__half2 h) {
    union { uint32_t u; __half2 h; } c; c.h = h; return c.u;
}
#define LDSM4(r0, r1, r2, r3, addr) \
    asm volatile("ldmatrix.sync.aligned.m8n8.x4.shared.b16 {%0,%1,%2,%3}, [%4];" \
                 : "=r"(r0), "=r"(r1), "=r"(r2), "=r"(r3) : "r"(addr))
#define MMA_F16(c, a0, a1, a2, a3, b0, b1) \
    asm volatile("mma.sync.aligned.m16n8k16.row.col.f32.f16.f16.f32 " \
                 "{%0,%1,%2,%3}, {%4,%5,%6,%7}, {%8,%9}, {%0,%1,%2,%3};" \
                 : "+f"((c)[0]), "+f"((c)[1]), "+f"((c)[2]), "+f"((c)[3]) \
                 : "r"(a0), "r"(a1), "r"(a2), "r"(a3), "r"(b0), "r"(b1))
#define CP_ASYNC16(dst, src) \
    asm volatile("cp.async.cg.shared.global [%0], [%1], 16;" \
                 :: "r"(dst), "l"(src) : "memory")
#define CP_COMMIT() asm volatile("cp.async.commit_group;" ::: "memory")
#define CP_WAIT1()  asm volatile("cp.async.wait_group 1;" ::: "memory")

// ---------------------------------------------------------------------------
// Kernel 0: pack adj into bitmask words. Ballot-style: one int per lane,
// 8 words per warp, all 8 loads issued up-front (MLP=8). No smem, low regs.
// ---------------------------------------------------------------------------
__global__ __launch_bounds__(256) void k0_pack(const int* __restrict__ adj) {
    const int warp_g = (blockIdx.x * 256 + threadIdx.x) >> 5;
    const int lane   = threadIdx.x & 31;
    const int* p = adj + (size_t)warp_g * 256 + lane;
    int v[8];
#pragma unroll
    for (int q = 0; q < 8; q++) v[q] = p[q * 32];
#pragma unroll
    for (int q = 0; q < 8; q++) {
        unsigned b = __ballot_sync(0xffffffffu, v[q] != 0);
        if (lane == 0) g_adjm[warp_g * 8 + q] = b;
    }
}

// ---------------------------------------------------------------------------
// Kernel 1 (fused scores): h-tile = x @ W, write fp16 hT + score tables.
// CTA = 1 head x 32 n-rows (full d=64). 128 threads: tx(16) x ty(8), 4x4 tile.
// ---------------------------------------------------------------------------
__global__ __launch_bounds__(128) void k1_fused(const float* __restrict__ x,
                                                const float* __restrict__ W,
                                                const float* __restrict__ a) {
    __shared__ float xs[64][36];
    __shared__ float ws[64][68];
    __shared__ float sr1[32][17];
    __shared__ float sr2[32][17];

    const int head = blockIdx.x;
    const int n0   = blockIdx.y * 32;
    const int tid  = threadIdx.x;
    const int tx   = tid & 15;
    const int ty   = tid >> 4;
    const float* Wh = W + (size_t)head * FIN * DHH;

    float c[4][4] = {};
    for (int f0 = 0; f0 < FIN; f0 += 64) {
        __syncthreads();
#pragma unroll
        for (int r = 0; r < 4; r++) {
            int idx = tid + r * 128;
            int row = idx >> 4;
            int c4  = idx & 15;
            float4 v = *(const float4*)(x + (size_t)(n0 + row) * FIN + f0 + c4 * 4);
            xs[c4 * 4 + 0][row] = v.x;
            xs[c4 * 4 + 1][row] = v.y;
            xs[c4 * 4 + 2][row] = v.z;
            xs[c4 * 4 + 3][row] = v.w;
        }
#pragma unroll
        for (int r = 0; r < 8; r++) {
            int idx = tid + r * 128;
            int row = idx >> 4;
            int c4  = idx & 15;
            *(float4*)&ws[row][c4 * 4] =
                *(const float4*)(Wh + (size_t)(f0 + row) * DHH + c4 * 4);
        }
        __syncthreads();
#pragma unroll 16
        for (int k = 0; k < 64; k++) {
            float4 av = *(const float4*)&xs[k][ty * 4];
            float4 bv = *(const float4*)&ws[k][tx * 4];
            const float aa[4] = {av.x, av.y, av.z, av.w};
            const float bb[4] = {bv.x, bv.y, bv.z, bv.w};
#pragma unroll
            for (int ii = 0; ii < 4; ii++)
#pragma unroll
                for (int jj = 0; jj < 4; jj++)
                    c[ii][jj] = fmaf(aa[ii], bb[jj], c[ii][jj]);
        }
    }

    __half* htb = g_hTh + (size_t)head * DHH * NN + n0 + ty * 4;
#pragma unroll
    for (int jj = 0; jj < 4; jj++) {
        __half2 p0 = __floats2half2_rn(c[0][jj], c[1][jj]);
        __half2 p1 = __floats2half2_rn(c[2][jj], c[3][jj]);
        uint2 u = make_uint2(h2u(p0), h2u(p1));
        *(uint2*)(htb + (size_t)(tx * 4 + jj) * NN) = u;
    }

    const float4 a1v = *(const float4*)(a + head * 2 * DHH + tx * 4);
    const float4 a2v = *(const float4*)(a + head * 2 * DHH + DHH + tx * 4);
#pragma unroll
    for (int ii = 0; ii < 4; ii++) {
        sr1[ty * 4 + ii][tx] = c[ii][0] * a1v.x + c[ii][1] * a1v.y +
                               c[ii][2] * a1v.z + c[ii][3] * a1v.w;
        sr2[ty * 4 + ii][tx] = c[ii][0] * a2v.x + c[ii][1] * a2v.y +
                               c[ii][2] * a2v.z + c[ii][3] * a2v.w;
    }
    __syncthreads();
    if (tid < 32) {
        float s1 = 0.f, s2 = 0.f;
#pragma unroll
        for (int q = 0; q < 16; q++) { s1 += sr1[tid][q]; s2 += sr2[tid][q]; }
        const int idx = head * NN + n0 + tid;
        g_ssrc[idx] = s1;
        g_E[idx] = __expf(s1);
        g_e[idx] = __expf(0.01f * s1);
        g_t_h[idx] = __float2half_rn(s2);
        g_F_h[idx] = __float2half_rn(__expf(s2));
        g_f_h[idx] = __float2half_rn(__expf(0.01f * s2));
    }
}

// ---------------------------------------------------------------------------
// Kernel 3: masked-softmax aggregation via mma.sync fp16 (fp32 accum).
// Grid (NH, NN/64, NSPLIT=4). UNCHANGED (proven).
// ---------------------------------------------------------------------------
#define TJ 64
#define JRANGE (NN / NSPLIT)
#define NT (JRANGE / TJ)
#define PITCH 72   // halves; 144B rows -> conflict-free ldmatrix

__global__ __launch_bounds__(128, 4) void k3_agg() {
    __shared__ __align__(16) __half sP[64 * PITCH];       // 9216 B
    __shared__ __align__(16) __half sB[2][64 * PITCH];    // 18432 B

    const int head  = blockIdx.x;
    const int i0    = blockIdx.y * 64;
    const int split = blockIdx.z;
    const int jbase = split * JRANGE;
    const int tid   = threadIdx.x;
    const int lane  = tid & 31;
    const int w     = tid >> 5;
    const int wr    = w >> 1;
    const int wc    = w & 1;
    const int i     = tid >> 1;
    const int jhalf = tid & 1;

    const int rowg = head * NN + i0 + i;
    const __half2 nsi2 = __float2half2_rn(-g_ssrc[rowg]);
    const __half2 Ei2  = __float2half2_rn(g_E[rowg]);
    const __half2 ei2  = __float2half2_rn(g_e[rowg]);
    const __half2 cap2 = __float2half2_rn(60000.f);
    const __half* tp = g_t_h + head * NN;
    const __half* Fp = g_F_h + head * NN;
    const __half* fp = g_f_h + head * NN;
    const unsigned* mrow = g_adjm + (size_t)(i0 + i) * NW + (jbase >> 5) + jhalf;
    const __half* hTh = g_hTh + (size_t)head * DHH * NN;

    const uint32_t sPu = smem_u32(sP);
    const uint32_t sBu = smem_u32(sB);
    const uint32_t lrow = lane & 15;
    const uint32_t lcol = (lane >> 4) * 8;
    const uint32_t aBase = sPu + ((wr * 32 + lrow) * PITCH + lcol) * 2;
    const uint32_t bBase = sBu + ((wc * 32 + lrow) * PITCH + lcol) * 2;

    float c[8][4] = {};
    float rs = 0.f;

#pragma unroll
    for (int k = 0; k < 4; k++) {
        int ch = tid + k * 128;
        int row = ch >> 3;
        int kc  = ch & 7;
        CP_ASYNC16(sBu + row * 144 + kc * 16,
                   hTh + (size_t)row * NN + jbase + kc * 8);
    }
    CP_COMMIT();

    for (int t = 0; t < NT; t++) {
        const int buf = t & 1;
        __syncthreads();

        if (t + 1 < NT) {
            const int j1 = jbase + (t + 1) * TJ;
            const uint32_t bb = sBu + (buf ^ 1) * 9216;
#pragma unroll
            for (int k = 0; k < 4; k++) {
                int ch = tid + k * 128;
                int row = ch >> 3;
                int kc  = ch & 7;
                CP_ASYNC16(bb + row * 144 + kc * 16,
                           hTh + (size_t)row * NN + j1 + kc * 8);
            }
        }
        CP_COMMIT();

        const int j0 = jbase + t * TJ;
        const unsigned m = mrow[t * 2];
        const uint4* tu = (const uint4*)(tp + j0 + jhalf * 32);
        const uint4* Fu = (const uint4*)(Fp + j0 + jhalf * 32);
        const uint4* fu = (const uint4*)(fp + j0 + jhalf * 32);
        const uint32_t pdst = sPu + i * 144 + jhalf * 64;
#pragma unroll
        for (int ch = 0; ch < 4; ch++) {
            uint4 tv = tu[ch], Fv = Fu[ch], fv = fu[ch];
            const uint32_t ta[4] = {tv.x, tv.y, tv.z, tv.w};
            const uint32_t Fa[4] = {Fv.x, Fv.y, Fv.z, Fv.w};
            const uint32_t fa[4] = {fv.x, fv.y, fv.z, fv.w};
            uint32_t vr[4];
#pragma unroll
            for (int u = 0; u < 4; u++) {
                __half2 cmp = __hgt2(u2h(ta[u]), nsi2);
                __half2 hiv = __hmul2(Ei2, u2h(Fa[u]));
                __half2 lov = __hmul2(ei2, u2h(fa[u]));
                __half2 v = __hfma2(cmp, __hsub2(hiv, lov), lov);
                v = __hmin2(v, cap2);
                unsigned bb2 = (m >> (ch * 8 + u * 2)) & 3u;
                unsigned mm = ((bb2 & 1u) * 0x3C00u) | ((bb2 >> 1) * 0x3C000000u);
                v = __hmul2(v, u2h(mm));
                float2 vf = __half22float2(v);
                rs += vf.x + vf.y;
                vr[u] = h2u(v);
            }
            asm volatile("st.shared.v4.b32 [%0], {%1,%2,%3,%4};"
                         :: "r"(pdst + ch * 16), "r"(vr[0]), "r"(vr[1]),
                            "r"(vr[2]), "r"(vr[3]) : "memory");
        }

        CP_WAIT1();
        __syncthreads();

        const uint32_t bB = bBase + buf * 9216;
#pragma unroll
        for (int ks = 0; ks < 4; ks++) {
            uint32_t a0, a1, a2, a3, a4, a5, a6, a7;
            LDSM4(a0, a1, a2, a3, aBase + ks * 32);
            LDSM4(a4, a5, a6, a7, aBase + 16 * PITCH * 2 + ks * 32);
#pragma unroll
            for (int q2 = 0; q2 < 2; q2++) {
                uint32_t b0, b1, b2, b3;
                LDSM4(b0, b1, b2, b3, bB + q2 * (16 * PITCH * 2) + ks * 32);
                MMA_F16(c[q2 * 2 + 0], a0, a1, a2, a3, b0, b2);
                MMA_F16(c[q2 * 2 + 1], a0, a1, a2, a3, b1, b3);
                MMA_F16(c[4 + q2 * 2 + 0], a4, a5, a6, a7, b0, b2);
                MMA_F16(c[4 + q2 * 2 + 1], a4, a5, a6, a7, b1, b3);
            }
        }
    }

    rs += __shfl_xor_sync(0xffffffffu, rs, 1);
    if (jhalf == 0)
        g_rsp[((size_t)split * NH + head) * NN + i0 + i] = rs;

    float* accb = g_acc + (((size_t)split * NH + head) * NN + i0) * DHH;
#pragma unroll
    for (int mi = 0; mi < 2; mi++) {
        const int r0 = wr * 32 + mi * 16 + (lane >> 2);
#pragma unroll
        for (int q2 = 0; q2 < 2; q2++)
#pragma unroll
            for (int nn2 = 0; nn2 < 2; nn2++) {
                const float* cf = c[mi * 4 + q2 * 2 + nn2];
                const int col = wc * 32 + q2 * 16 + nn2 * 8 + (lane & 3) * 2;
                *(float2*)(accb + (size_t)r0 * DHH + col) =
                    make_float2(cf[0], cf[1]);
                *(float2*)(accb + (size_t)(r0 + 8) * DHH + col) =
                    make_float2(cf[2], cf[3]);
            }
    }
}

// ---------------------------------------------------------------------------
// Kernel 4: combine 4 split partials, normalize, ELU, store (vectorized).
// ---------------------------------------------------------------------------
__global__ __launch_bounds__(256) void k4_fin(float* __restrict__ out) {
    const int g    = blockIdx.x * 256 + threadIdx.x;   // float4 index
    const int n    = g >> 6;
    const int rem  = g & 63;
    const int head = rem >> 4;
    const int d4   = rem & 15;

    float4 acc = make_float4(0.f, 0.f, 0.f, 0.f);
    float r = 0.f;
#pragma unroll
    for (int s = 0; s < NSPLIT; s++) {
        const float4 v = *(const float4*)(g_acc +
            (((size_t)s * NH + head) * NN + n) * DHH + d4 * 4);
        acc.x += v.x; acc.y += v.y; acc.z += v.z; acc.w += v.w;
        r += g_rsp[((size_t)s * NH + head) * NN + n];
    }
    const float inv = 1.0f / r;
    float z0 = acc.x * inv, z1 = acc.y * inv, z2 = acc.z * inv, z3 = acc.w * inv;
    z0 = z0 > 0.f ? z0 : expm1f(z0);
    z1 = z1 > 0.f ? z1 : expm1f(z1);
    z2 = z2 > 0.f ? z2 : expm1f(z2);
    z3 = z3 > 0.f ? z3 : expm1f(z3);
    *(float4*)(out + (size_t)g * 4) = make_float4(z0, z1, z2, z3);
}

// ---------------------------------------------------------------------------
extern "C" void kernel_launch(void* const* d_in, const int* in_sizes, int n_in,
                              void* d_out, int out_size) {
    (void)in_sizes; (void)n_in; (void)out_size;
    const float* x   = (const float*)d_in[0];
    const int*   adj = (const int*)d_in[1];
    const float* W   = (const float*)d_in[2];
    const float* a   = (const float*)d_in[3];
    float* out = (float*)d_out;

    static cudaStream_t s2;
    static cudaEvent_t evFork, evJoin;
    static bool init = false;
    if (!init) {
        cudaStreamCreateWithFlags(&s2, cudaStreamNonBlocking);
        cudaEventCreateWithFlags(&evFork, cudaEventDisableTiming);
        cudaEventCreateWithFlags(&evJoin, cudaEventDisableTiming);
        init = true;
    }

    // fork: k0 (DRAM-bound) on s2 concurrent with k1 (FMA-bound) on main
    cudaEventRecord(evFork, 0);
    cudaStreamWaitEvent(s2, evFork, 0);
    k0_pack <<<NN * NW / (8 * 8), 256, 0, s2>>>(adj);   // 8192 blocks
    k1_fused<<<dim3(NH, NN / 32), 128>>>(x, W, a);
    cudaEventRecord(evJoin, s2);
    cudaStreamWaitEvent(0, evJoin, 0);

    k3_agg<<<dim3(NH, NN / 64, NSPLIT), 128>>>();
    k4_fin<<<NN * NH * DHH / 1024, 256>>>(out);
}

// round 13
// speedup vs baseline: 1.2051x; 1.2051x over previous
#include <cuda_runtime.h>
#include <cuda_fp16.h>
#include <cstdint>

#define NN   4096
#define FIN  256
#define NH   4
#define DHH  64
#define NW   (NN / 32)      // 128 adj-mask words per row
#define NSPLIT 4

// ------------------------- device globals (no alloc allowed) ---------------
__device__ __half g_hTh[NH * DHH * NN];   // hT[head][d][n] fp16
__device__ float  g_ssrc[NH * NN];
__device__ float  g_E[NH * NN];           // exp(s_src)
__device__ float  g_e[NH * NN];           // exp(0.01*s_src)
__device__ __half g_t_h[NH * NN];         // s_dst (half)
__device__ __half g_F_h[NH * NN];         // exp(s_dst)
__device__ __half g_f_h[NH * NN];         // exp(0.01*s_dst)
__device__ unsigned g_adjm[NN * NW];      // adjacency bitmask
__device__ float  g_acc[NSPLIT * NH * NN * DHH];  // unnormalized partials
__device__ float  g_rsp[NSPLIT * NH * NN];        // rowsum partials

// ------------------------- helpers -----------------------------------------
__device__ __forceinline__ uint32_t smem_u32(const void* p) {
    uint32_t a;
    asm("{ .reg .u64 t; cvta.to.shared.u64 t, %1; cvt.u32.u64 %0, t; }"
        : "=r"(a) : "l"(p));
    return a;
}
__device__ __forceinline__ __half2 u2h(uint32_t u) {
    union { uint32_t u; __half2 h; } c; c.u = u; return c.h;
}
__device__ __forceinline__ uint32_t h2u(__half2 h) {
    union { uint32_t u; __half2 h; } c; c.h = h; return c.u;
}
#define LDSM4(r0, r1, r2, r3, addr) \
    asm volatile("ldmatrix.sync.aligned.m8n8.x4.shared.b16 {%0,%1,%2,%3}, [%4];" \
                 : "=r"(r0), "=r"(r1), "=r"(r2), "=r"(r3) : "r"(addr))
#define MMA_F16(c, a0, a1, a2, a3, b0, b1) \
    asm volatile("mma.sync.aligned.m16n8k16.row.col.f32.f16.f16.f32 " \
                 "{%0,%1,%2,%3}, {%4,%5,%6,%7}, {%8,%9}, {%0,%1,%2,%3};" \
                 : "+f"((c)[0]), "+f"((c)[1]), "+f"((c)[2]), "+f"((c)[3]) \
                 : "r"(a0), "r"(a1), "r"(a2), "r"(a3), "r"(b0), "r"(b1))
#define CP_ASYNC16(dst, src) \
    asm volatile("cp.async.cg.shared.global [%0], [%1], 16;" \
                 :: "r"(dst), "l"(src) : "memory")
#define CP_COMMIT() asm volatile("cp.async.commit_group;" ::: "memory")
#define CP_WAIT1()  asm volatile("cp.async.wait_group 1;" ::: "memory")

// ---------------------------------------------------------------------------
// Kernel 0: pack adj into bitmask words. Ballot-style: one int per lane
// (fully coalesced 128B per warp per iteration), 8 words per warp, all 8
// loads issued up-front (MLP=8). No smem, low regs -> full occupancy.
// ---------------------------------------------------------------------------
__global__ __launch_bounds__(256) void k0_pack(const int* __restrict__ adj) {
    const int warp_g = (blockIdx.x * 256 + threadIdx.x) >> 5;
    const int lane   = threadIdx.x & 31;
    const int* p = adj + (size_t)warp_g * 256 + lane;
    int v[8];
#pragma unroll
    for (int q = 0; q < 8; q++) v[q] = p[q * 32];
#pragma unroll
    for (int q = 0; q < 8; q++) {
        unsigned b = __ballot_sync(0xffffffffu, v[q] != 0);
        if (lane == 0) g_adjm[warp_g * 8 + q] = b;
    }
}

// ---------------------------------------------------------------------------
// Kernel 1 (fused scores): h-tile = x @ W, write fp16 hT + score tables.
// CTA = 1 head x 32 n-rows (full d=64). 128 threads: tx(16) x ty(8), 4x4 tile.
// ---------------------------------------------------------------------------
__global__ __launch_bounds__(128) void k1_fused(const float* __restrict__ x,
                                                const float* __restrict__ W,
                                                const float* __restrict__ a) {
    __shared__ float xs[64][36];
    __shared__ float ws[64][68];
    __shared__ float sr1[32][17];
    __shared__ float sr2[32][17];

    const int head = blockIdx.x;
    const int n0   = blockIdx.y * 32;
    const int tid  = threadIdx.x;
    const int tx   = tid & 15;
    const int ty   = tid >> 4;
    const float* Wh = W + (size_t)head * FIN * DHH;

    float c[4][4] = {};
    for (int f0 = 0; f0 < FIN; f0 += 64) {
        __syncthreads();
#pragma unroll
        for (int r = 0; r < 4; r++) {
            int idx = tid + r * 128;
            int row = idx >> 4;
            int c4  = idx & 15;
            float4 v = *(const float4*)(x + (size_t)(n0 + row) * FIN + f0 + c4 * 4);
            xs[c4 * 4 + 0][row] = v.x;
            xs[c4 * 4 + 1][row] = v.y;
            xs[c4 * 4 + 2][row] = v.z;
            xs[c4 * 4 + 3][row] = v.w;
        }
#pragma unroll
        for (int r = 0; r < 8; r++) {
            int idx = tid + r * 128;
            int row = idx >> 4;
            int c4  = idx & 15;
            *(float4*)&ws[row][c4 * 4] =
                *(const float4*)(Wh + (size_t)(f0 + row) * DHH + c4 * 4);
        }
        __syncthreads();
#pragma unroll 16
        for (int k = 0; k < 64; k++) {
            float4 av = *(const float4*)&xs[k][ty * 4];
            float4 bv = *(const float4*)&ws[k][tx * 4];
            const float aa[4] = {av.x, av.y, av.z, av.w};
            const float bb[4] = {bv.x, bv.y, bv.z, bv.w};
#pragma unroll
            for (int ii = 0; ii < 4; ii++)
#pragma unroll
                for (int jj = 0; jj < 4; jj++)
                    c[ii][jj] = fmaf(aa[ii], bb[jj], c[ii][jj]);
        }
    }

    __half* htb = g_hTh + (size_t)head * DHH * NN + n0 + ty * 4;
#pragma unroll
    for (int jj = 0; jj < 4; jj++) {
        __half2 p0 = __floats2half2_rn(c[0][jj], c[1][jj]);
        __half2 p1 = __floats2half2_rn(c[2][jj], c[3][jj]);
        uint2 u = make_uint2(h2u(p0), h2u(p1));
        *(uint2*)(htb + (size_t)(tx * 4 + jj) * NN) = u;
    }

    const float4 a1v = *(const float4*)(a + head * 2 * DHH + tx * 4);
    const float4 a2v = *(const float4*)(a + head * 2 * DHH + DHH + tx * 4);
#pragma unroll
    for (int ii = 0; ii < 4; ii++) {
        sr1[ty * 4 + ii][tx] = c[ii][0] * a1v.x + c[ii][1] * a1v.y +
                               c[ii][2] * a1v.z + c[ii][3] * a1v.w;
        sr2[ty * 4 + ii][tx] = c[ii][0] * a2v.x + c[ii][1] * a2v.y +
                               c[ii][2] * a2v.z + c[ii][3] * a2v.w;
    }
    __syncthreads();
    if (tid < 32) {
        float s1 = 0.f, s2 = 0.f;
#pragma unroll
        for (int q = 0; q < 16; q++) { s1 += sr1[tid][q]; s2 += sr2[tid][q]; }
        const int idx = head * NN + n0 + tid;
        g_ssrc[idx] = s1;
        g_E[idx] = __expf(s1);
        g_e[idx] = __expf(0.01f * s1);
        g_t_h[idx] = __float2half_rn(s2);
        g_F_h[idx] = __float2half_rn(__expf(s2));
        g_f_h[idx] = __float2half_rn(__expf(0.01f * s2));
    }
}

// ---------------------------------------------------------------------------
// Kernel 3: masked-softmax aggregation via mma.sync fp16 (fp32 accum).
// Grid (NH, NN/64, NSPLIT=4). UNCHANGED (proven).
// ---------------------------------------------------------------------------
#define TJ 64
#define JRANGE (NN / NSPLIT)
#define NT (JRANGE / TJ)
#define PITCH 72   // halves; 144B rows -> conflict-free ldmatrix

__global__ __launch_bounds__(128, 4) void k3_agg() {
    __shared__ __align__(16) __half sP[64 * PITCH];       // 9216 B
    __shared__ __align__(16) __half sB[2][64 * PITCH];    // 18432 B

    const int head  = blockIdx.x;
    const int i0    = blockIdx.y * 64;
    const int split = blockIdx.z;
    const int jbase = split * JRANGE;
    const int tid   = threadIdx.x;
    const int lane  = tid & 31;
    const int w     = tid >> 5;
    const int wr    = w >> 1;
    const int wc    = w & 1;
    const int i     = tid >> 1;
    const int jhalf = tid & 1;

    const int rowg = head * NN + i0 + i;
    const __half2 nsi2 = __float2half2_rn(-g_ssrc[rowg]);
    const __half2 Ei2  = __float2half2_rn(g_E[rowg]);
    const __half2 ei2  = __float2half2_rn(g_e[rowg]);
    const __half2 cap2 = __float2half2_rn(60000.f);
    const __half* tp = g_t_h + head * NN;
    const __half* Fp = g_F_h + head * NN;
    const __half* fp = g_f_h + head * NN;
    const unsigned* mrow = g_adjm + (size_t)(i0 + i) * NW + (jbase >> 5) + jhalf;
    const __half* hTh = g_hTh + (size_t)head * DHH * NN;

    const uint32_t sPu = smem_u32(sP);
    const uint32_t sBu = smem_u32(sB);
    const uint32_t lrow = lane & 15;
    const uint32_t lcol = (lane >> 4) * 8;
    const uint32_t aBase = sPu + ((wr * 32 + lrow) * PITCH + lcol) * 2;
    const uint32_t bBase = sBu + ((wc * 32 + lrow) * PITCH + lcol) * 2;

    float c[8][4] = {};
    float rs = 0.f;

#pragma unroll
    for (int k = 0; k < 4; k++) {
        int ch = tid + k * 128;
        int row = ch >> 3;
        int kc  = ch & 7;
        CP_ASYNC16(sBu + row * 144 + kc * 16,
                   hTh + (size_t)row * NN + jbase + kc * 8);
    }
    CP_COMMIT();

    for (int t = 0; t < NT; t++) {
        const int buf = t & 1;
        __syncthreads();

        if (t + 1 < NT) {
            const int j1 = jbase + (t + 1) * TJ;
            const uint32_t bb = sBu + (buf ^ 1) * 9216;
#pragma unroll
            for (int k = 0; k < 4; k++) {
                int ch = tid + k * 128;
                int row = ch >> 3;
                int kc  = ch & 7;
                CP_ASYNC16(bb + row * 144 + kc * 16,
                           hTh + (size_t)row * NN + j1 + kc * 8);
            }
        }
        CP_COMMIT();

        const int j0 = jbase + t * TJ;
        const unsigned m = mrow[t * 2];
        const uint4* tu = (const uint4*)(tp + j0 + jhalf * 32);
        const uint4* Fu = (const uint4*)(Fp + j0 + jhalf * 32);
        const uint4* fu = (const uint4*)(fp + j0 + jhalf * 32);
        const uint32_t pdst = sPu + i * 144 + jhalf * 64;
#pragma unroll
        for (int ch = 0; ch < 4; ch++) {
            uint4 tv = tu[ch], Fv = Fu[ch], fv = fu[ch];
            const uint32_t ta[4] = {tv.x, tv.y, tv.z, tv.w};
            const uint32_t Fa[4] = {Fv.x, Fv.y, Fv.z, Fv.w};
            const uint32_t fa[4] = {fv.x, fv.y, fv.z, fv.w};
            uint32_t vr[4];
#pragma unroll
            for (int u = 0; u < 4; u++) {
                __half2 cmp = __hgt2(u2h(ta[u]), nsi2);
                __half2 hiv = __hmul2(Ei2, u2h(Fa[u]));
                __half2 lov = __hmul2(ei2, u2h(fa[u]));
                __half2 v = __hfma2(cmp, __hsub2(hiv, lov), lov);
                v = __hmin2(v, cap2);
                unsigned bb2 = (m >> (ch * 8 + u * 2)) & 3u;
                unsigned mm = ((bb2 & 1u) * 0x3C00u) | ((bb2 >> 1) * 0x3C000000u);
                v = __hmul2(v, u2h(mm));
                float2 vf = __half22float2(v);
                rs += vf.x + vf.y;
                vr[u] = h2u(v);
            }
            asm volatile("st.shared.v4.b32 [%0], {%1,%2,%3,%4};"
                         :: "r"(pdst + ch * 16), "r"(vr[0]), "r"(vr[1]),
                            "r"(vr[2]), "r"(vr[3]) : "memory");
        }

        CP_WAIT1();
        __syncthreads();

        const uint32_t bB = bBase + buf * 9216;
#pragma unroll
        for (int ks = 0; ks < 4; ks++) {
            uint32_t a0, a1, a2, a3, a4, a5, a6, a7;
            LDSM4(a0, a1, a2, a3, aBase + ks * 32);
            LDSM4(a4, a5, a6, a7, aBase + 16 * PITCH * 2 + ks * 32);
#pragma unroll
            for (int q2 = 0; q2 < 2; q2++) {
                uint32_t b0, b1, b2, b3;
                LDSM4(b0, b1, b2, b3, bB + q2 * (16 * PITCH * 2) + ks * 32);
                MMA_F16(c[q2 * 2 + 0], a0, a1, a2, a3, b0, b2);
                MMA_F16(c[q2 * 2 + 1], a0, a1, a2, a3, b1, b3);
                MMA_F16(c[4 + q2 * 2 + 0], a4, a5, a6, a7, b0, b2);
                MMA_F16(c[4 + q2 * 2 + 1], a4, a5, a6, a7, b1, b3);
            }
        }
    }

    rs += __shfl_xor_sync(0xffffffffu, rs, 1);
    if (jhalf == 0)
        g_rsp[((size_t)split * NH + head) * NN + i0 + i] = rs;

    float* accb = g_acc + (((size_t)split * NH + head) * NN + i0) * DHH;
#pragma unroll
    for (int mi = 0; mi < 2; mi++) {
        const int r0 = wr * 32 + mi * 16 + (lane >> 2);
#pragma unroll
        for (int q2 = 0; q2 < 2; q2++)
#pragma unroll
            for (int nn2 = 0; nn2 < 2; nn2++) {
                const float* cf = c[mi * 4 + q2 * 2 + nn2];
                const int col = wc * 32 + q2 * 16 + nn2 * 8 + (lane & 3) * 2;
                *(float2*)(accb + (size_t)r0 * DHH + col) =
                    make_float2(cf[0], cf[1]);
                *(float2*)(accb + (size_t)(r0 + 8) * DHH + col) =
                    make_float2(cf[2], cf[3]);
            }
    }
}

// ---------------------------------------------------------------------------
// Kernel 4: combine 4 split partials, normalize, ELU, store (vectorized).
// ---------------------------------------------------------------------------
__global__ __launch_bounds__(256) void k4_fin(float* __restrict__ out) {
    const int g    = blockIdx.x * 256 + threadIdx.x;   // float4 index
    const int n    = g >> 6;
    const int rem  = g & 63;
    const int head = rem >> 4;
    const int d4   = rem & 15;

    float4 acc = make_float4(0.f, 0.f, 0.f, 0.f);
    float r = 0.f;
#pragma unroll
    for (int s = 0; s < NSPLIT; s++) {
        const float4 v = *(const float4*)(g_acc +
            (((size_t)s * NH + head) * NN + n) * DHH + d4 * 4);
        acc.x += v.x; acc.y += v.y; acc.z += v.z; acc.w += v.w;
        r += g_rsp[((size_t)s * NH + head) * NN + n];
    }
    const float inv = 1.0f / r;
    float z0 = acc.x * inv, z1 = acc.y * inv, z2 = acc.z * inv, z3 = acc.w * inv;
    z0 = z0 > 0.f ? z0 : expm1f(z0);
    z1 = z1 > 0.f ? z1 : expm1f(z1);
    z2 = z2 > 0.f ? z2 : expm1f(z2);
    z3 = z3 > 0.f ? z3 : expm1f(z3);
    *(float4*)(out + (size_t)g * 4) = make_float4(z0, z1, z2, z3);
}

// ---------------------------------------------------------------------------
extern "C" void kernel_launch(void* const* d_in, const int* in_sizes, int n_in,
                              void* d_out, int out_size) {
    (void)in_sizes; (void)n_in; (void)out_size;
    const float* x   = (const float*)d_in[0];
    const int*   adj = (const int*)d_in[1];
    const float* W   = (const float*)d_in[2];
    const float* a   = (const float*)d_in[3];
    float* out = (float*)d_out;

    k0_pack <<<NN * NW / (8 * 8), 256>>>(adj);          // 8192 blocks
    k1_fused<<<dim3(NH, NN / 32), 128>>>(x, W, a);
    k3_agg  <<<dim3(NH, NN / 64, NSPLIT), 128>>>();
    k4_fin  <<<NN * NH * DHH / 1024, 256>>>(out);
}

// round 14
// speedup vs baseline: 1.2168x; 1.0096x over previous
#include <cuda_runtime.h>
#include <cuda_fp16.h>
#include <cstdint>

#define NN   4096
#define FIN  256
#define NH   4
#define DHH  64
#define NW   (NN / 32)      // 128 adj-mask words per row
#define NSPLIT 4

// ------------------------- device globals (no alloc allowed) ---------------
__device__ __half g_hTh[NH * DHH * NN];   // hT[head][d][n] fp16
__device__ float  g_ssrc[NH * NN];
__device__ float  g_E[NH * NN];           // exp(s_src)
__device__ float  g_e[NH * NN];           // exp(0.01*s_src)
__device__ __half g_t_h[NH * NN];         // s_dst (half)
__device__ __half g_F_h[NH * NN];         // exp(s_dst)
__device__ __half g_f_h[NH * NN];         // exp(0.01*s_dst)
__device__ unsigned g_adjm[NN * NW];      // adjacency bitmask
__device__ float  g_acc[NSPLIT * NH * NN * DHH];  // unnormalized partials
__device__ float  g_rsp[NSPLIT * NH * NN];        // rowsum partials

// ------------------------- helpers -----------------------------------------
__device__ __forceinline__ uint32_t smem_u32(const void* p) {
    uint32_t a;
    asm("{ .reg .u64 t; cvta.to.shared.u64 t, %1; cvt.u32.u64 %0, t; }"
        : "=r"(a) : "l"(p));
    return a;
}
__device__ __forceinline__ __half2 u2h(uint32_t u) {
    union { uint32_t u; __half2 h; } c; c.u = u; return c.h;
}
__device__ __forceinline__ uint32_t h2u(__half2 h) {
    union { uint32_t u; __half2 h; } c; c.h = h; return c.u;
}
#define LDSM4(r0, r1, r2, r3, addr) \
    asm volatile("ldmatrix.sync.aligned.m8n8.x4.shared.b16 {%0,%1,%2,%3}, [%4];" \
                 : "=r"(r0), "=r"(r1), "=r"(r2), "=r"(r3) : "r"(addr))
#define MMA_F16(c, a0, a1, a2, a3, b0, b1) \
    asm volatile("mma.sync.aligned.m16n8k16.row.col.f32.f16.f16.f32 " \
                 "{%0,%1,%2,%3}, {%4,%5,%6,%7}, {%8,%9}, {%0,%1,%2,%3};" \
                 : "+f"((c)[0]), "+f"((c)[1]), "+f"((c)[2]), "+f"((c)[3]) \
                 : "r"(a0), "r"(a1), "r"(a2), "r"(a3), "r"(b0), "r"(b1))
#define CP_ASYNC16(dst, src) \
    asm volatile("cp.async.cg.shared.global [%0], [%1], 16;" \
                 :: "r"(dst), "l"(src) : "memory")
#define CP_COMMIT() asm volatile("cp.async.commit_group;" ::: "memory")
#define CP_WAIT1()  asm volatile("cp.async.wait_group 1;" ::: "memory")

// ---------------------------------------------------------------------------
// Kernel 0: pack adj into bitmask words. Ballot-style, fully coalesced.
// ---------------------------------------------------------------------------
__global__ __launch_bounds__(256) void k0_pack(const int* __restrict__ adj) {
    const int warp_g = (blockIdx.x * 256 + threadIdx.x) >> 5;
    const int lane   = threadIdx.x & 31;
    const int* p = adj + (size_t)warp_g * 256 + lane;
    int v[8];
#pragma unroll
    for (int q = 0; q < 8; q++) v[q] = p[q * 32];
#pragma unroll
    for (int q = 0; q < 8; q++) {
        unsigned b = __ballot_sync(0xffffffffu, v[q] != 0);
        if (lane == 0) g_adjm[warp_g * 8 + q] = b;
    }
}

// ---------------------------------------------------------------------------
// Kernel 1 (fused scores): h-tile = x @ W, write fp16 hT + score tables.
// ---------------------------------------------------------------------------
__global__ __launch_bounds__(128) void k1_fused(const float* __restrict__ x,
                                                const float* __restrict__ W,
                                                const float* __restrict__ a) {
    __shared__ float xs[64][36];
    __shared__ float ws[64][68];
    __shared__ float sr1[32][17];
    __shared__ float sr2[32][17];

    const int head = blockIdx.x;
    const int n0   = blockIdx.y * 32;
    const int tid  = threadIdx.x;
    const int tx   = tid & 15;
    const int ty   = tid >> 4;
    const float* Wh = W + (size_t)head * FIN * DHH;

    float c[4][4] = {};
    for (int f0 = 0; f0 < FIN; f0 += 64) {
        __syncthreads();
#pragma unroll
        for (int r = 0; r < 4; r++) {
            int idx = tid + r * 128;
            int row = idx >> 4;
            int c4  = idx & 15;
            float4 v = *(const float4*)(x + (size_t)(n0 + row) * FIN + f0 + c4 * 4);
            xs[c4 * 4 + 0][row] = v.x;
            xs[c4 * 4 + 1][row] = v.y;
            xs[c4 * 4 + 2][row] = v.z;
            xs[c4 * 4 + 3][row] = v.w;
        }
#pragma unroll
        for (int r = 0; r < 8; r++) {
            int idx = tid + r * 128;
            int row = idx >> 4;
            int c4  = idx & 15;
            *(float4*)&ws[row][c4 * 4] =
                *(const float4*)(Wh + (size_t)(f0 + row) * DHH + c4 * 4);
        }
        __syncthreads();
#pragma unroll 16
        for (int k = 0; k < 64; k++) {
            float4 av = *(const float4*)&xs[k][ty * 4];
            float4 bv = *(const float4*)&ws[k][tx * 4];
            const float aa[4] = {av.x, av.y, av.z, av.w};
            const float bb[4] = {bv.x, bv.y, bv.z, bv.w};
#pragma unroll
            for (int ii = 0; ii < 4; ii++)
#pragma unroll
                for (int jj = 0; jj < 4; jj++)
                    c[ii][jj] = fmaf(aa[ii], bb[jj], c[ii][jj]);
        }
    }

    __half* htb = g_hTh + (size_t)head * DHH * NN + n0 + ty * 4;
#pragma unroll
    for (int jj = 0; jj < 4; jj++) {
        __half2 p0 = __floats2half2_rn(c[0][jj], c[1][jj]);
        __half2 p1 = __floats2half2_rn(c[2][jj], c[3][jj]);
        uint2 u = make_uint2(h2u(p0), h2u(p1));
        *(uint2*)(htb + (size_t)(tx * 4 + jj) * NN) = u;
    }

    const float4 a1v = *(const float4*)(a + head * 2 * DHH + tx * 4);
    const float4 a2v = *(const float4*)(a + head * 2 * DHH + DHH + tx * 4);
#pragma unroll
    for (int ii = 0; ii < 4; ii++) {
        sr1[ty * 4 + ii][tx] = c[ii][0] * a1v.x + c[ii][1] * a1v.y +
                               c[ii][2] * a1v.z + c[ii][3] * a1v.w;
        sr2[ty * 4 + ii][tx] = c[ii][0] * a2v.x + c[ii][1] * a2v.y +
                               c[ii][2] * a2v.z + c[ii][3] * a2v.w;
    }
    __syncthreads();
    if (tid < 32) {
        float s1 = 0.f, s2 = 0.f;
#pragma unroll
        for (int q = 0; q < 16; q++) { s1 += sr1[tid][q]; s2 += sr2[tid][q]; }
        const int idx = head * NN + n0 + tid;
        g_ssrc[idx] = s1;
        g_E[idx] = __expf(s1);
        g_e[idx] = __expf(0.01f * s1);
        g_t_h[idx] = __float2half_rn(s2);
        g_F_h[idx] = __float2half_rn(__expf(s2));
        g_f_h[idx] = __float2half_rn(__expf(0.01f * s2));
    }
}

// ---------------------------------------------------------------------------
// Kernel 3: masked-softmax aggregation via mma.sync fp16 (fp32 accum).
// Grid (NH, NN/64, NSPLIT=4). 4 warps, each 32i x 32d.
// ONE __syncthreads per tile: sP double-buffered, sB triple-buffered.
// (Skew <= 1 iter; buffer indices of writers/readers provably disjoint.)
// ---------------------------------------------------------------------------
#define TJ 64
#define JRANGE (NN / NSPLIT)
#define NT (JRANGE / TJ)
#define PITCH 72        // halves; 144B rows -> conflict-free ldmatrix
#define TILE_B 9216     // 64 * PITCH * 2 bytes

__global__ __launch_bounds__(128, 4) void k3_agg() {
    __shared__ __align__(16) __half sP[2][64 * PITCH];    // 18432 B
    __shared__ __align__(16) __half sB[3][64 * PITCH];    // 27648 B

    const int head  = blockIdx.x;
    const int i0    = blockIdx.y * 64;
    const int split = blockIdx.z;
    const int jbase = split * JRANGE;
    const int tid   = threadIdx.x;
    const int lane  = tid & 31;
    const int w     = tid >> 5;
    const int wr    = w >> 1;
    const int wc    = w & 1;
    const int i     = tid >> 1;
    const int jhalf = tid & 1;

    const int rowg = head * NN + i0 + i;
    const __half2 nsi2 = __float2half2_rn(-g_ssrc[rowg]);
    const __half2 Ei2  = __float2half2_rn(g_E[rowg]);
    const __half2 ei2  = __float2half2_rn(g_e[rowg]);
    const __half2 cap2 = __float2half2_rn(60000.f);
    const __half* tp = g_t_h + head * NN;
    const __half* Fp = g_F_h + head * NN;
    const __half* fp = g_f_h + head * NN;
    const unsigned* mrow = g_adjm + (size_t)(i0 + i) * NW + (jbase >> 5) + jhalf;
    const __half* hTh = g_hTh + (size_t)head * DHH * NN;

    const uint32_t sPu = smem_u32(sP);
    const uint32_t sBu = smem_u32(sB);
    const uint32_t lrow = lane & 15;
    const uint32_t lcol = (lane >> 4) * 8;
    const uint32_t aBase = sPu + ((wr * 32 + lrow) * PITCH + lcol) * 2;
    const uint32_t bBase = sBu + ((wc * 32 + lrow) * PITCH + lcol) * 2;

    float c[8][4] = {};
    float rs = 0.f;

    // ---- preload B tile 0 into sB[0] ----
#pragma unroll
    for (int k = 0; k < 4; k++) {
        int ch = tid + k * 128;
        int row = ch >> 3;
        int kc  = ch & 7;
        CP_ASYNC16(sBu + row * 144 + kc * 16,
                   hTh + (size_t)row * NN + jbase + kc * 8);
    }
    CP_COMMIT();

    int bcur = 0;
    for (int t = 0; t < NT; t++) {
        const int bnext = (bcur == 2) ? 0 : bcur + 1;
        const int sbuf  = t & 1;

        // ---- prefetch B tile t+1 into sB[bnext] ----
        if (t + 1 < NT) {
            const int j1 = jbase + (t + 1) * TJ;
            const uint32_t bb = sBu + bnext * TILE_B;
#pragma unroll
            for (int k = 0; k < 4; k++) {
                int ch = tid + k * 128;
                int row = ch >> 3;
                int kc  = ch & 7;
                CP_ASYNC16(bb + row * 144 + kc * 16,
                           hTh + (size_t)row * NN + j1 + kc * 8);
            }
        }
        CP_COMMIT();

        // ---- P phase -> sP[sbuf] (safe: all readers of sP[sbuf] finished
        //      at sync(t-1); skew bounded by the single barrier) ----
        const int j0 = jbase + t * TJ;
        const unsigned m = mrow[t * 2];
        const uint4* tu = (const uint4*)(tp + j0 + jhalf * 32);
        const uint4* Fu = (const uint4*)(Fp + j0 + jhalf * 32);
        const uint4* fu = (const uint4*)(fp + j0 + jhalf * 32);
        const uint32_t pdst = sPu + sbuf * TILE_B + i * 144 + jhalf * 64;
#pragma unroll
        for (int ch = 0; ch < 4; ch++) {
            uint4 tv = tu[ch], Fv = Fu[ch], fv = fu[ch];
            const uint32_t ta[4] = {tv.x, tv.y, tv.z, tv.w};
            const uint32_t Fa[4] = {Fv.x, Fv.y, Fv.z, Fv.w};
            const uint32_t fa[4] = {fv.x, fv.y, fv.z, fv.w};
            uint32_t vr[4];
#pragma unroll
            for (int u = 0; u < 4; u++) {
                __half2 cmp = __hgt2(u2h(ta[u]), nsi2);
                __half2 hiv = __hmul2(Ei2, u2h(Fa[u]));
                __half2 lov = __hmul2(ei2, u2h(fa[u]));
                __half2 v = __hfma2(cmp, __hsub2(hiv, lov), lov);
                v = __hmin2(v, cap2);
                unsigned bb2 = (m >> (ch * 8 + u * 2)) & 3u;
                unsigned mm = ((bb2 & 1u) * 0x3C00u) | ((bb2 >> 1) * 0x3C000000u);
                v = __hmul2(v, u2h(mm));
                float2 vf = __half22float2(v);
                rs += vf.x + vf.y;
                vr[u] = h2u(v);
            }
            asm volatile("st.shared.v4.b32 [%0], {%1,%2,%3,%4};"
                         :: "r"(pdst + ch * 16), "r"(vr[0]), "r"(vr[1]),
                            "r"(vr[2]), "r"(vr[3]) : "memory");
        }

        CP_WAIT1();          // B tile t complete (one group outstanding)
        __syncthreads();     // the single barrier: sP[sbuf]+sB[bcur] visible

        // ---- MMA: reads sP[sbuf], sB[bcur] ----
        const uint32_t aA = aBase + sbuf * TILE_B;
        const uint32_t bB = bBase + bcur * TILE_B;
#pragma unroll
        for (int ks = 0; ks < 4; ks++) {
            uint32_t a0, a1, a2, a3, a4, a5, a6, a7;
            LDSM4(a0, a1, a2, a3, aA + ks * 32);
            LDSM4(a4, a5, a6, a7, aA + 16 * PITCH * 2 + ks * 32);
#pragma unroll
            for (int q2 = 0; q2 < 2; q2++) {
                uint32_t b0, b1, b2, b3;
                LDSM4(b0, b1, b2, b3, bB + q2 * (16 * PITCH * 2) + ks * 32);
                MMA_F16(c[q2 * 2 + 0], a0, a1, a2, a3, b0, b2);
                MMA_F16(c[q2 * 2 + 1], a0, a1, a2, a3, b1, b3);
                MMA_F16(c[4 + q2 * 2 + 0], a4, a5, a6, a7, b0, b2);
                MMA_F16(c[4 + q2 * 2 + 1], a4, a5, a6, a7, b1, b3);
            }
        }
        bcur = bnext;
    }

    rs += __shfl_xor_sync(0xffffffffu, rs, 1);
    if (jhalf == 0)
        g_rsp[((size_t)split * NH + head) * NN + i0 + i] = rs;

    float* accb = g_acc + (((size_t)split * NH + head) * NN + i0) * DHH;
#pragma unroll
    for (int mi = 0; mi < 2; mi++) {
        const int r0 = wr * 32 + mi * 16 + (lane >> 2);
#pragma unroll
        for (int q2 = 0; q2 < 2; q2++)
#pragma unroll
            for (int nn2 = 0; nn2 < 2; nn2++) {
                const float* cf = c[mi * 4 + q2 * 2 + nn2];
                const int col = wc * 32 + q2 * 16 + nn2 * 8 + (lane & 3) * 2;
                *(float2*)(accb + (size_t)r0 * DHH + col) =
                    make_float2(cf[0], cf[1]);
                *(float2*)(accb + (size_t)(r0 + 8) * DHH + col) =
                    make_float2(cf[2], cf[3]);
            }
    }
}

// ---------------------------------------------------------------------------
// Kernel 4: combine 4 split partials, normalize, ELU, store (vectorized).
// ---------------------------------------------------------------------------
__global__ __launch_bounds__(256) void k4_fin(float* __restrict__ out) {
    const int g    = blockIdx.x * 256 + threadIdx.x;   // float4 index
    const int n    = g >> 6;
    const int rem  = g & 63;
    const int head = rem >> 4;
    const int d4   = rem & 15;

    float4 acc = make_float4(0.f, 0.f, 0.f, 0.f);
    float r = 0.f;
#pragma unroll
    for (int s = 0; s < NSPLIT; s++) {
        const float4 v = *(const float4*)(g_acc +
            (((size_t)s * NH + head) * NN + n) * DHH + d4 * 4);
        acc.x += v.x; acc.y += v.y; acc.z += v.z; acc.w += v.w;
        r += g_rsp[((size_t)s * NH + head) * NN + n];
    }
    const float inv = 1.0f / r;
    float z0 = acc.x * inv, z1 = acc.y * inv, z2 = acc.z * inv, z3 = acc.w * inv;
    z0 = z0 > 0.f ? z0 : expm1f(z0);
    z1 = z1 > 0.f ? z1 : expm1f(z1);
    z2 = z2 > 0.f ? z2 : expm1f(z2);
    z3 = z3 > 0.f ? z3 : expm1f(z3);
    *(float4*)(out + (size_t)g * 4) = make_float4(z0, z1, z2, z3);
}

// ---------------------------------------------------------------------------
extern "C" void kernel_launch(void* const* d_in, const int* in_sizes, int n_in,
                              void* d_out, int out_size) {
    (void)in_sizes; (void)n_in; (void)out_size;
    const float* x   = (const float*)d_in[0];
    const int*   adj = (const int*)d_in[1];
    const float* W   = (const float*)d_in[2];
    const float* a   = (const float*)d_in[3];
    float* out = (float*)d_out;

    k0_pack <<<NN * NW / (8 * 8), 256>>>(adj);
    k1_fused<<<dim3(NH, NN / 32), 128>>>(x, W, a);
    k3_agg  <<<dim3(NH, NN / 64, NSPLIT), 128>>>();
    k4_fin  <<<NN * NH * DHH / 1024, 256>>>(out);
}